// round 4
// baseline (speedup 1.0000x reference)
#include <cuda_runtime.h>
#include <cuda_bf16.h>
#include <cstdint>

#define E_ 8
#define H_ 1024
#define I_ 2048
#define T_ 1024

#define KB   32          // K floats per stage chunk
#define KST  36          // padded smem row stride (floats): conflict-free, 16B-aligned rows (144B)
#define STG  ((128 + 128) * KST)        // floats per stage (A 128 rows + B 128 rows)
#define SMEMSZ (2 * STG * 4)            // 73728 bytes, 2 stages

// ---------------- scratch (device globals; no allocation allowed) ----------------
__device__ int   g_cnt[E_];
__device__ int   g_tok[E_ * T_];
__device__ int   g_slot[E_ * T_];
__device__ float g_gate[E_ * T_];
__device__ float g_xtf[T_ * H_];                   // x pre-rounded to tf32
__device__ float g_act[(size_t)E_ * T_ * I_];      // tf32-exact activations
__device__ float g_ypart[(size_t)T_ * 2 * H_];

// ---------------- helpers ----------------
__device__ __forceinline__ void cp16(void* s, const void* g) {
    uint32_t sa = (uint32_t)__cvta_generic_to_shared(s);
    asm volatile("cp.async.cg.shared.global [%0], [%1], 16;\n" :: "r"(sa), "l"(g));
}
__device__ __forceinline__ void cp_commit() { asm volatile("cp.async.commit_group;\n"); }
__device__ __forceinline__ void cp_wait0()  { asm volatile("cp.async.wait_group 0;\n"); }

__device__ __forceinline__ uint32_t f2tf(float f) {
    uint32_t u;
    asm("cvt.rna.tf32.f32 %0, %1;" : "=r"(u) : "f"(f));
    return u;
}
__device__ __forceinline__ void mma8(float c[4], const uint32_t a[4], const uint32_t b[2]) {
    asm volatile(
        "mma.sync.aligned.m16n8k8.row.col.f32.tf32.tf32.f32 "
        "{%0,%1,%2,%3}, {%4,%5,%6,%7}, {%8,%9}, {%0,%1,%2,%3};\n"
        : "+f"(c[0]), "+f"(c[1]), "+f"(c[2]), "+f"(c[3])
        : "r"(a[0]), "r"(a[1]), "r"(a[2]), "r"(a[3]), "r"(b[0]), "r"(b[1]));
}
__device__ __forceinline__ uint32_t fbits(float f) { return __float_as_uint(f); }

// ---------------- small kernels ----------------
__global__ void zero_cnt_kernel() { if (threadIdx.x < E_) g_cnt[threadIdx.x] = 0; }

__global__ void preround_kernel(const float* __restrict__ x) {
    int i = blockIdx.x * blockDim.x + threadIdx.x;    // T_*H_/4 elems
    float4 v = reinterpret_cast<const float4*>(x)[i];
    float4 o;
    o.x = __uint_as_float(f2tf(v.x)); o.y = __uint_as_float(f2tf(v.y));
    o.z = __uint_as_float(f2tf(v.z)); o.w = __uint_as_float(f2tf(v.w));
    reinterpret_cast<float4*>(g_xtf)[i] = o;
}

__global__ void router_kernel(const float* __restrict__ logits) {
    int t = blockIdx.x * blockDim.x + threadIdx.x;
    if (t >= T_) return;
    float l[E_]; float mx = -1e30f;
#pragma unroll
    for (int e = 0; e < E_; e++) { l[e] = logits[t * E_ + e]; mx = fmaxf(mx, l[e]); }
    float p[E_];
#pragma unroll
    for (int e = 0; e < E_; e++) p[e] = __expf(l[e] - mx);
    int i1 = 0, i2 = -1; float v1 = p[0], v2 = -1.0f;
#pragma unroll
    for (int e = 1; e < E_; e++) {
        float pe = p[e];
        if (pe > v1) { v2 = v1; i2 = i1; v1 = pe; i1 = e; }
        else if (pe > v2) { v2 = pe; i2 = e; }
    }
    float inv = 1.0f / (v1 + v2);
    int pos1 = atomicAdd(&g_cnt[i1], 1);
    g_tok[i1 * T_ + pos1] = t; g_slot[i1 * T_ + pos1] = 0; g_gate[i1 * T_ + pos1] = v1 * inv;
    int pos2 = atomicAdd(&g_cnt[i2], 1);
    g_tok[i2 * T_ + pos2] = t; g_slot[i2 * T_ + pos2] = 1; g_gate[i2 * T_ + pos2] = v2 * inv;
}

// ================= GEMM1: 128m x 64n dual (G|L), fused GLU =================
// smem stage: A[128][KST] then B[128][KST] (B rows 0..63 = G, 64..127 = L)
__global__ void __launch_bounds__(256, 2) gemm1_kernel(
    const float* __restrict__ w13, const float* __restrict__ b13)
{
    int e = blockIdx.z;
    int cnt = g_cnt[e];
    int m0 = blockIdx.y * 128;
    if (m0 >= cnt) return;
    int n0 = blockIdx.x * 64;
    int tid = threadIdx.x;

    extern __shared__ float sm[];

    // loaders: thread -> row (tid>>1) of A and of B, 4 x cp16 each at (tid&1)*16 + j*4
    int lrow = tid >> 1;
    int lcol = (tid & 1) * 16;
    int mg = m0 + lrow; if (mg >= cnt) mg = cnt - 1;
    const float* aptr = g_xtf + (size_t)g_tok[e * T_ + mg] * H_ + lcol;
    size_t browg = (lrow < 64) ? ((size_t)e * 2 * I_ + n0 + lrow)
                               : ((size_t)e * 2 * I_ + I_ + n0 + (lrow - 64));
    const float* bptr = w13 + browg * H_ + lcol;
    float* adst = sm + lrow * KST + lcol;
    float* bdst = sm + 128 * KST + lrow * KST + lcol;

#define FILL1(c, s) {                                                   \
        float* ad_ = adst + (s) * STG; float* bd_ = bdst + (s) * STG;   \
        const float* ap_ = aptr + (c) * KB;                             \
        const float* bp_ = bptr + (c) * KB;                             \
        cp16(ad_, ap_); cp16(ad_ + 4, ap_ + 4);                         \
        cp16(ad_ + 8, ap_ + 8); cp16(ad_ + 12, ap_ + 12);               \
        cp16(bd_, bp_); cp16(bd_ + 4, bp_ + 4);                         \
        cp16(bd_ + 8, bp_ + 8); cp16(bd_ + 12, bp_ + 12);               \
        cp_commit(); }

    float accG[2][4][4], accL[2][4][4];
#pragma unroll
    for (int i = 0; i < 2; i++)
#pragma unroll
        for (int j = 0; j < 4; j++)
#pragma unroll
            for (int k = 0; k < 4; k++) { accG[i][j][k] = 0.f; accL[i][j][k] = 0.f; }

    int lane = tid & 31, warp = tid >> 5;
    int wm = warp & 3, wn = warp >> 2;        // 4m x 2n warps; warp tile 32m x 32n (G and L)
    int gid = lane >> 2, tig = lane & 3;

    FILL1(0, 0);
    const int NK = H_ / KB;   // 32
#pragma unroll 1
    for (int kt = 0; kt < NK; ++kt) {
        int st = kt & 1;
        cp_wait0();
        __syncthreads();
        if (kt + 1 < NK) FILL1(kt + 1, st ^ 1);
        const float* base = sm + st * STG;
#pragma unroll
        for (int ks = 0; ks < 4; ++ks) {
            int kk = ks * 8;
            uint32_t a[2][4];
#pragma unroll
            for (int mi = 0; mi < 2; mi++) {
                const float* ap = base + (wm * 32 + mi * 16 + gid) * KST + kk + tig;
                a[mi][0] = fbits(ap[0]);
                a[mi][1] = fbits(ap[8 * KST]);
                a[mi][2] = fbits(ap[4]);
                a[mi][3] = fbits(ap[8 * KST + 4]);
            }
#pragma unroll
            for (int ni = 0; ni < 4; ni++) {
                const float* bp = base + 128 * KST + (wn * 32 + ni * 8 + gid) * KST + kk + tig;
                uint32_t bg[2] = { fbits(bp[0]), fbits(bp[4]) };
                uint32_t bl[2] = { fbits(bp[64 * KST]), fbits(bp[64 * KST + 4]) };
#pragma unroll
                for (int mi = 0; mi < 2; mi++) {
                    mma8(accG[mi][ni], a[mi], bg);
                    mma8(accL[mi][ni], a[mi], bl);
                }
            }
        }
    }

    // epilogue: bias + GLU + tf32-round + store
    float bgv[4][2], blv[4][2];
#pragma unroll
    for (int ni = 0; ni < 4; ni++) {
        int n = n0 + wn * 32 + ni * 8 + tig * 2;
        bgv[ni][0] = __ldg(&b13[(size_t)e * 2 * I_ + n]);
        bgv[ni][1] = __ldg(&b13[(size_t)e * 2 * I_ + n + 1]);
        blv[ni][0] = __ldg(&b13[(size_t)e * 2 * I_ + I_ + n]);
        blv[ni][1] = __ldg(&b13[(size_t)e * 2 * I_ + I_ + n + 1]);
    }
    size_t actbase = (size_t)e * T_ * I_;
#pragma unroll
    for (int mi = 0; mi < 2; mi++) {
#pragma unroll
        for (int rr = 0; rr < 2; rr++) {
            int m = m0 + wm * 32 + mi * 16 + gid + rr * 8;
            if (m >= cnt) continue;
            float* actrow = g_act + actbase + (size_t)m * I_;
#pragma unroll
            for (int ni = 0; ni < 4; ni++) {
                int n = n0 + wn * 32 + ni * 8 + tig * 2;
                float g0 = accG[mi][ni][rr * 2 + 0] + bgv[ni][0];
                float g1 = accG[mi][ni][rr * 2 + 1] + bgv[ni][1];
                float l0 = accL[mi][ni][rr * 2 + 0] + blv[ni][0];
                float l1 = accL[mi][ni][rr * 2 + 1] + blv[ni][1];
                float a0 = g0 * (1.f / (1.f + __expf(-1.702f * g0))) * (l0 + 1.0f);
                float a1 = g1 * (1.f / (1.f + __expf(-1.702f * g1))) * (l1 + 1.0f);
                *reinterpret_cast<float2*>(actrow + n) =
                    make_float2(__uint_as_float(f2tf(a0)), __uint_as_float(f2tf(a1)));
            }
        }
    }
}

// ================= GEMM2: 128m x 128n, fused bias+gate+scatter =================
__global__ void __launch_bounds__(256, 2) gemm2_kernel(
    const float* __restrict__ w2, const float* __restrict__ b2)
{
    int e = blockIdx.z;
    int cnt = g_cnt[e];
    int m0 = blockIdx.y * 128;
    if (m0 >= cnt) return;
    int n0 = blockIdx.x * 128;
    int tid = threadIdx.x;

    extern __shared__ float sm[];

    int lrow = tid >> 1;
    int lcol = (tid & 1) * 16;
    const float* aptr = g_act + (size_t)(e * T_ + m0 + lrow) * I_ + lcol;
    const float* bptr = w2 + (size_t)(e * H_ + n0 + lrow) * I_ + lcol;
    float* adst = sm + lrow * KST + lcol;
    float* bdst = sm + 128 * KST + lrow * KST + lcol;

#define FILL2(c, s) {                                                   \
        float* ad_ = adst + (s) * STG; float* bd_ = bdst + (s) * STG;   \
        const float* ap_ = aptr + (c) * KB;                             \
        const float* bp_ = bptr + (c) * KB;                             \
        cp16(ad_, ap_); cp16(ad_ + 4, ap_ + 4);                         \
        cp16(ad_ + 8, ap_ + 8); cp16(ad_ + 12, ap_ + 12);               \
        cp16(bd_, bp_); cp16(bd_ + 4, bp_ + 4);                         \
        cp16(bd_ + 8, bp_ + 8); cp16(bd_ + 12, bp_ + 12);               \
        cp_commit(); }

    float acc[2][8][4];
#pragma unroll
    for (int i = 0; i < 2; i++)
#pragma unroll
        for (int j = 0; j < 8; j++)
#pragma unroll
            for (int k = 0; k < 4; k++) acc[i][j][k] = 0.f;

    int lane = tid & 31, warp = tid >> 5;
    int wm = warp & 3, wn = warp >> 2;        // 4m x 2n warps; warp tile 32m x 64n
    int gid = lane >> 2, tig = lane & 3;

    FILL2(0, 0);
    const int NK = I_ / KB;   // 64
#pragma unroll 1
    for (int kt = 0; kt < NK; ++kt) {
        int st = kt & 1;
        cp_wait0();
        __syncthreads();
        if (kt + 1 < NK) FILL2(kt + 1, st ^ 1);
        const float* base = sm + st * STG;
#pragma unroll
        for (int ks = 0; ks < 4; ++ks) {
            int kk = ks * 8;
            uint32_t a[2][4];
#pragma unroll
            for (int mi = 0; mi < 2; mi++) {
                const float* ap = base + (wm * 32 + mi * 16 + gid) * KST + kk + tig;
                a[mi][0] = fbits(ap[0]);
                a[mi][1] = fbits(ap[8 * KST]);
                a[mi][2] = fbits(ap[4]);
                a[mi][3] = fbits(ap[8 * KST + 4]);
            }
#pragma unroll
            for (int ni = 0; ni < 8; ni++) {
                const float* bp = base + 128 * KST + (wn * 64 + ni * 8 + gid) * KST + kk + tig;
                uint32_t b[2] = { fbits(bp[0]), fbits(bp[4]) };
#pragma unroll
                for (int mi = 0; mi < 2; mi++) mma8(acc[mi][ni], a[mi], b);
            }
        }
    }

    float bv[8][2];
#pragma unroll
    for (int ni = 0; ni < 8; ni++) {
        int n = n0 + wn * 64 + ni * 8 + tig * 2;
        bv[ni][0] = __ldg(&b2[(size_t)e * H_ + n]);
        bv[ni][1] = __ldg(&b2[(size_t)e * H_ + n + 1]);
    }
#pragma unroll
    for (int mi = 0; mi < 2; mi++) {
#pragma unroll
        for (int rr = 0; rr < 2; rr++) {
            int m = m0 + wm * 32 + mi * 16 + gid + rr * 8;
            if (m >= cnt) continue;
            int tok = g_tok[e * T_ + m];
            int slot = g_slot[e * T_ + m];
            float gt = g_gate[e * T_ + m];
            float* dst = g_ypart + (size_t)(tok * 2 + slot) * H_;
#pragma unroll
            for (int ni = 0; ni < 8; ni++) {
                int n = n0 + wn * 64 + ni * 8 + tig * 2;
                float v0 = (acc[mi][ni][rr * 2 + 0] + bv[ni][0]) * gt;
                float v1 = (acc[mi][ni][rr * 2 + 1] + bv[ni][1]) * gt;
                *reinterpret_cast<float2*>(dst + n) = make_float2(v0, v1);
            }
        }
    }
}

// ---------------- deterministic combine ----------------
__global__ void combine_kernel(float* __restrict__ out) {
    int i = blockIdx.x * blockDim.x + threadIdx.x;
    const int HV = H_ / 4;
    int t = i / HV;
    int h = i - t * HV;
    const float4* p0 = reinterpret_cast<const float4*>(g_ypart) + (size_t)(2 * t) * HV + h;
    const float4* p1 = p0 + HV;
    float4 a = *p0, b = *p1;
    reinterpret_cast<float4*>(out)[i] = make_float4(a.x + b.x, a.y + b.y, a.z + b.z, a.w + b.w);
}

// ---------------- launch ----------------
extern "C" void kernel_launch(void* const* d_in, const int* in_sizes, int n_in,
                              void* d_out, int out_size) {
    const float* x      = (const float*)d_in[0];
    const float* logits = (const float*)d_in[1];
    const float* w13    = (const float*)d_in[2];
    const float* w2     = (const float*)d_in[3];
    const float* b13    = (const float*)d_in[4];
    const float* b2     = (const float*)d_in[5];
    float* out = (float*)d_out;

    static int attr_done = 0;
    if (!attr_done) {
        cudaFuncSetAttribute(gemm1_kernel, cudaFuncAttributeMaxDynamicSharedMemorySize, SMEMSZ);
        cudaFuncSetAttribute(gemm2_kernel, cudaFuncAttributeMaxDynamicSharedMemorySize, SMEMSZ);
        attr_done = 1;
    }

    zero_cnt_kernel<<<1, 32>>>();
    preround_kernel<<<(T_ * H_ / 4) / 256, 256>>>(x);
    router_kernel<<<T_ / 256, 256>>>(logits);

    dim3 g1(I_ / 64, T_ / 128, E_);    // 32 x 8 x 8
    gemm1_kernel<<<g1, 256, SMEMSZ>>>(w13, b13);

    dim3 g2(H_ / 128, T_ / 128, E_);   // 8 x 8 x 8
    gemm2_kernel<<<g2, 256, SMEMSZ>>>(w2, b2);

    combine_kernel<<<(T_ * H_ / 4) / 256, 256>>>(out);
}

// round 5
// speedup vs baseline: 1.0040x; 1.0040x over previous
#include <cuda_runtime.h>
#include <cuda_bf16.h>
#include <cstdint>

#define E_ 8
#define H_ 1024
#define I_ 2048
#define T_ 1024

#define KB   32          // K floats per stage chunk
#define KST  36          // padded smem row stride (floats): conflict-free, rows 144B
#define STG  ((128 + 128) * KST)        // floats per stage (A 128 rows + B 128 rows)
#define NSTG 3
#define SMEMSZ (NSTG * STG * 4)         // 110592 bytes

// ---------------- scratch (device globals; no allocation allowed) ----------------
__device__ int   g_cnt[E_];
__device__ int   g_tok[E_ * T_];
__device__ int   g_slot[E_ * T_];
__device__ float g_gate[E_ * T_];
__device__ float g_xtf[T_ * H_];                   // x pre-rounded to tf32
__device__ float g_act[(size_t)E_ * T_ * I_];      // tf32-exact activations
__device__ float g_ypart[(size_t)T_ * 2 * H_];

// ---------------- helpers ----------------
__device__ __forceinline__ void cp16(void* s, const void* g) {
    uint32_t sa = (uint32_t)__cvta_generic_to_shared(s);
    asm volatile("cp.async.cg.shared.global [%0], [%1], 16;\n" :: "r"(sa), "l"(g));
}
__device__ __forceinline__ void cp_commit() { asm volatile("cp.async.commit_group;\n"); }
__device__ __forceinline__ void cp_wait1()  { asm volatile("cp.async.wait_group 1;\n"); }

__device__ __forceinline__ uint32_t f2tf(float f) {
    uint32_t u;
    asm("cvt.rna.tf32.f32 %0, %1;" : "=r"(u) : "f"(f));
    return u;
}
__device__ __forceinline__ void mma8(float c[4], const uint32_t a[4], const uint32_t b[2]) {
    asm volatile(
        "mma.sync.aligned.m16n8k8.row.col.f32.tf32.tf32.f32 "
        "{%0,%1,%2,%3}, {%4,%5,%6,%7}, {%8,%9}, {%0,%1,%2,%3};\n"
        : "+f"(c[0]), "+f"(c[1]), "+f"(c[2]), "+f"(c[3])
        : "r"(a[0]), "r"(a[1]), "r"(a[2]), "r"(a[3]), "r"(b[0]), "r"(b[1]));
}
__device__ __forceinline__ uint32_t fbits(float f) { return __float_as_uint(f); }

// ---------------- small kernels ----------------
__global__ void zero_cnt_kernel() { if (threadIdx.x < E_) g_cnt[threadIdx.x] = 0; }

__global__ void preround_kernel(const float* __restrict__ x) {
    int i = blockIdx.x * blockDim.x + threadIdx.x;    // T_*H_/4 elems
    float4 v = reinterpret_cast<const float4*>(x)[i];
    float4 o;
    o.x = __uint_as_float(f2tf(v.x)); o.y = __uint_as_float(f2tf(v.y));
    o.z = __uint_as_float(f2tf(v.z)); o.w = __uint_as_float(f2tf(v.w));
    reinterpret_cast<float4*>(g_xtf)[i] = o;
}

__global__ void router_kernel(const float* __restrict__ logits) {
    int t = blockIdx.x * blockDim.x + threadIdx.x;
    if (t >= T_) return;
    float l[E_]; float mx = -1e30f;
#pragma unroll
    for (int e = 0; e < E_; e++) { l[e] = logits[t * E_ + e]; mx = fmaxf(mx, l[e]); }
    float p[E_];
#pragma unroll
    for (int e = 0; e < E_; e++) p[e] = __expf(l[e] - mx);
    int i1 = 0, i2 = -1; float v1 = p[0], v2 = -1.0f;
#pragma unroll
    for (int e = 1; e < E_; e++) {
        float pe = p[e];
        if (pe > v1) { v2 = v1; i2 = i1; v1 = pe; i1 = e; }
        else if (pe > v2) { v2 = pe; i2 = e; }
    }
    float inv = 1.0f / (v1 + v2);
    int pos1 = atomicAdd(&g_cnt[i1], 1);
    g_tok[i1 * T_ + pos1] = t; g_slot[i1 * T_ + pos1] = 0; g_gate[i1 * T_ + pos1] = v1 * inv;
    int pos2 = atomicAdd(&g_cnt[i2], 1);
    g_tok[i2 * T_ + pos2] = t; g_slot[i2 * T_ + pos2] = 1; g_gate[i2 * T_ + pos2] = v2 * inv;
}

// ================= GEMM1: 128m x 64n dual (G|L), fused GLU =================
__global__ void __launch_bounds__(256, 2) gemm1_kernel(
    const float* __restrict__ w13, const float* __restrict__ b13)
{
    int e = blockIdx.z;
    int cnt = g_cnt[e];
    int m0 = blockIdx.y * 128;
    if (m0 >= cnt) return;
    int n0 = blockIdx.x * 64;
    int tid = threadIdx.x;

    extern __shared__ float sm[];

    // loaders: thread -> row (tid>>1), half-row 16 floats at (tid&1)*16
    int lrow = tid >> 1;
    int lcol = (tid & 1) * 16;
    int mg = m0 + lrow; if (mg >= cnt) mg = cnt - 1;
    const float* aptr = g_xtf + (size_t)g_tok[e * T_ + mg] * H_ + lcol;
    size_t browg = (lrow < 64) ? ((size_t)e * 2 * I_ + n0 + lrow)
                               : ((size_t)e * 2 * I_ + I_ + n0 + (lrow - 64));
    const float* bptr = w13 + browg * H_ + lcol;
    float* adst = sm + lrow * KST + lcol;
    float* bdst = sm + 128 * KST + lrow * KST + lcol;

#define FILL1(c, s) {                                                   \
        float* ad_ = adst + (s) * STG; float* bd_ = bdst + (s) * STG;   \
        const float* ap_ = aptr + (c) * KB;                             \
        const float* bp_ = bptr + (c) * KB;                             \
        cp16(ad_, ap_); cp16(ad_ + 4, ap_ + 4);                         \
        cp16(ad_ + 8, ap_ + 8); cp16(ad_ + 12, ap_ + 12);               \
        cp16(bd_, bp_); cp16(bd_ + 4, bp_ + 4);                         \
        cp16(bd_ + 8, bp_ + 8); cp16(bd_ + 12, bp_ + 12);               \
        cp_commit(); }

    float accG[2][4][4], accL[2][4][4];
#pragma unroll
    for (int i = 0; i < 2; i++)
#pragma unroll
        for (int j = 0; j < 4; j++)
#pragma unroll
            for (int k = 0; k < 4; k++) { accG[i][j][k] = 0.f; accL[i][j][k] = 0.f; }

    int lane = tid & 31, warp = tid >> 5;
    int wm = warp & 3, wn = warp >> 2;        // 4m x 2n warps; warp tile 32m x 32n (G and L)
    int gid = lane >> 2, tig = lane & 3;

    // prologue: chunks 0,1 into stages 0,1
    FILL1(0, 0);
    FILL1(1, 1);

    const int NK = H_ / KB;   // 32
#pragma unroll 1
    for (int kt = 0; kt < NK; ++kt) {
        int st = kt % NSTG;
        cp_wait1();              // chunk kt resident (newest pending = kt+1)
        __syncthreads();         // all warps done with stage (kt-1)%NSTG == (kt+2)%NSTG
        int cf = kt + 2;
        if (cf < NK) { FILL1(cf, cf % NSTG); } else { cp_commit(); }
        const float* base = sm + st * STG;
#pragma unroll
        for (int ks = 0; ks < 4; ++ks) {
            int kk = ks * 8;
            uint32_t a[2][4];
#pragma unroll
            for (int mi = 0; mi < 2; mi++) {
                const float* ap = base + (wm * 32 + mi * 16 + gid) * KST + kk + tig;
                a[mi][0] = fbits(ap[0]);
                a[mi][1] = fbits(ap[8 * KST]);
                a[mi][2] = fbits(ap[4]);
                a[mi][3] = fbits(ap[8 * KST + 4]);
            }
#pragma unroll
            for (int ni = 0; ni < 4; ni++) {
                const float* bp = base + 128 * KST + (wn * 32 + ni * 8 + gid) * KST + kk + tig;
                uint32_t bg[2] = { fbits(bp[0]), fbits(bp[4]) };
                uint32_t bl[2] = { fbits(bp[64 * KST]), fbits(bp[64 * KST + 4]) };
#pragma unroll
                for (int mi = 0; mi < 2; mi++) {
                    mma8(accG[mi][ni], a[mi], bg);
                    mma8(accL[mi][ni], a[mi], bl);
                }
            }
        }
    }

    // epilogue: bias + GLU + tf32-round + store
    float bgv[4][2], blv[4][2];
#pragma unroll
    for (int ni = 0; ni < 4; ni++) {
        int n = n0 + wn * 32 + ni * 8 + tig * 2;
        bgv[ni][0] = __ldg(&b13[(size_t)e * 2 * I_ + n]);
        bgv[ni][1] = __ldg(&b13[(size_t)e * 2 * I_ + n + 1]);
        blv[ni][0] = __ldg(&b13[(size_t)e * 2 * I_ + I_ + n]);
        blv[ni][1] = __ldg(&b13[(size_t)e * 2 * I_ + I_ + n + 1]);
    }
    size_t actbase = (size_t)e * T_ * I_;
#pragma unroll
    for (int mi = 0; mi < 2; mi++) {
#pragma unroll
        for (int rr = 0; rr < 2; rr++) {
            int m = m0 + wm * 32 + mi * 16 + gid + rr * 8;
            if (m >= cnt) continue;
            float* actrow = g_act + actbase + (size_t)m * I_;
#pragma unroll
            for (int ni = 0; ni < 4; ni++) {
                int n = n0 + wn * 32 + ni * 8 + tig * 2;
                float g0 = accG[mi][ni][rr * 2 + 0] + bgv[ni][0];
                float g1 = accG[mi][ni][rr * 2 + 1] + bgv[ni][1];
                float l0 = accL[mi][ni][rr * 2 + 0] + blv[ni][0];
                float l1 = accL[mi][ni][rr * 2 + 1] + blv[ni][1];
                float a0 = g0 * (1.f / (1.f + __expf(-1.702f * g0))) * (l0 + 1.0f);
                float a1 = g1 * (1.f / (1.f + __expf(-1.702f * g1))) * (l1 + 1.0f);
                *reinterpret_cast<float2*>(actrow + n) =
                    make_float2(__uint_as_float(f2tf(a0)), __uint_as_float(f2tf(a1)));
            }
        }
    }
}

// ================= GEMM2: 128m x 128n, fused bias+gate+scatter =================
__global__ void __launch_bounds__(256, 2) gemm2_kernel(
    const float* __restrict__ w2, const float* __restrict__ b2)
{
    int e = blockIdx.z;
    int cnt = g_cnt[e];
    int m0 = blockIdx.y * 128;
    if (m0 >= cnt) return;
    int n0 = blockIdx.x * 128;
    int tid = threadIdx.x;

    extern __shared__ float sm[];

    int lrow = tid >> 1;
    int lcol = (tid & 1) * 16;
    const float* aptr = g_act + (size_t)(e * T_ + m0 + lrow) * I_ + lcol;
    const float* bptr = w2 + (size_t)(e * H_ + n0 + lrow) * I_ + lcol;
    float* adst = sm + lrow * KST + lcol;
    float* bdst = sm + 128 * KST + lrow * KST + lcol;

#define FILL2(c, s) {                                                   \
        float* ad_ = adst + (s) * STG; float* bd_ = bdst + (s) * STG;   \
        const float* ap_ = aptr + (c) * KB;                             \
        const float* bp_ = bptr + (c) * KB;                             \
        cp16(ad_, ap_); cp16(ad_ + 4, ap_ + 4);                         \
        cp16(ad_ + 8, ap_ + 8); cp16(ad_ + 12, ap_ + 12);               \
        cp16(bd_, bp_); cp16(bd_ + 4, bp_ + 4);                         \
        cp16(bd_ + 8, bp_ + 8); cp16(bd_ + 12, bp_ + 12);               \
        cp_commit(); }

    float acc[2][8][4];
#pragma unroll
    for (int i = 0; i < 2; i++)
#pragma unroll
        for (int j = 0; j < 8; j++)
#pragma unroll
            for (int k = 0; k < 4; k++) acc[i][j][k] = 0.f;

    int lane = tid & 31, warp = tid >> 5;
    int wm = warp & 3, wn = warp >> 2;        // 4m x 2n warps; warp tile 32m x 64n
    int gid = lane >> 2, tig = lane & 3;

    FILL2(0, 0);
    FILL2(1, 1);

    const int NK = I_ / KB;   // 64
#pragma unroll 1
    for (int kt = 0; kt < NK; ++kt) {
        int st = kt % NSTG;
        cp_wait1();
        __syncthreads();
        int cf = kt + 2;
        if (cf < NK) { FILL2(cf, cf % NSTG); } else { cp_commit(); }
        const float* base = sm + st * STG;
#pragma unroll
        for (int ks = 0; ks < 4; ++ks) {
            int kk = ks * 8;
            uint32_t a[2][4];
#pragma unroll
            for (int mi = 0; mi < 2; mi++) {
                const float* ap = base + (wm * 32 + mi * 16 + gid) * KST + kk + tig;
                a[mi][0] = fbits(ap[0]);
                a[mi][1] = fbits(ap[8 * KST]);
                a[mi][2] = fbits(ap[4]);
                a[mi][3] = fbits(ap[8 * KST + 4]);
            }
#pragma unroll
            for (int ni = 0; ni < 8; ni++) {
                const float* bp = base + 128 * KST + (wn * 64 + ni * 8 + gid) * KST + kk + tig;
                uint32_t b[2] = { fbits(bp[0]), fbits(bp[4]) };
#pragma unroll
                for (int mi = 0; mi < 2; mi++) mma8(acc[mi][ni], a[mi], b);
            }
        }
    }

    float bv[8][2];
#pragma unroll
    for (int ni = 0; ni < 8; ni++) {
        int n = n0 + wn * 64 + ni * 8 + tig * 2;
        bv[ni][0] = __ldg(&b2[(size_t)e * H_ + n]);
        bv[ni][1] = __ldg(&b2[(size_t)e * H_ + n + 1]);
    }
#pragma unroll
    for (int mi = 0; mi < 2; mi++) {
#pragma unroll
        for (int rr = 0; rr < 2; rr++) {
            int m = m0 + wm * 32 + mi * 16 + gid + rr * 8;
            if (m >= cnt) continue;
            int tok = g_tok[e * T_ + m];
            int slot = g_slot[e * T_ + m];
            float gt = g_gate[e * T_ + m];
            float* dst = g_ypart + (size_t)(tok * 2 + slot) * H_;
#pragma unroll
            for (int ni = 0; ni < 8; ni++) {
                int n = n0 + wn * 64 + ni * 8 + tig * 2;
                float v0 = (acc[mi][ni][rr * 2 + 0] + bv[ni][0]) * gt;
                float v1 = (acc[mi][ni][rr * 2 + 1] + bv[ni][1]) * gt;
                *reinterpret_cast<float2*>(dst + n) = make_float2(v0, v1);
            }
        }
    }
}

// ---------------- deterministic combine ----------------
__global__ void combine_kernel(float* __restrict__ out) {
    int i = blockIdx.x * blockDim.x + threadIdx.x;
    const int HV = H_ / 4;
    int t = i / HV;
    int h = i - t * HV;
    const float4* p0 = reinterpret_cast<const float4*>(g_ypart) + (size_t)(2 * t) * HV + h;
    const float4* p1 = p0 + HV;
    float4 a = *p0, b = *p1;
    reinterpret_cast<float4*>(out)[i] = make_float4(a.x + b.x, a.y + b.y, a.z + b.z, a.w + b.w);
}

// ---------------- launch ----------------
extern "C" void kernel_launch(void* const* d_in, const int* in_sizes, int n_in,
                              void* d_out, int out_size) {
    const float* x      = (const float*)d_in[0];
    const float* logits = (const float*)d_in[1];
    const float* w13    = (const float*)d_in[2];
    const float* w2     = (const float*)d_in[3];
    const float* b13    = (const float*)d_in[4];
    const float* b2     = (const float*)d_in[5];
    float* out = (float*)d_out;

    static int attr_done = 0;
    if (!attr_done) {
        cudaFuncSetAttribute(gemm1_kernel, cudaFuncAttributeMaxDynamicSharedMemorySize, SMEMSZ);
        cudaFuncSetAttribute(gemm2_kernel, cudaFuncAttributeMaxDynamicSharedMemorySize, SMEMSZ);
        attr_done = 1;
    }

    zero_cnt_kernel<<<1, 32>>>();
    preround_kernel<<<(T_ * H_ / 4) / 256, 256>>>(x);
    router_kernel<<<T_ / 256, 256>>>(logits);

    dim3 g1(I_ / 64, T_ / 128, E_);    // 32 x 8 x 8
    gemm1_kernel<<<g1, 256, SMEMSZ>>>(w13, b13);

    dim3 g2(H_ / 128, T_ / 128, E_);   // 8 x 8 x 8
    gemm2_kernel<<<g2, 256, SMEMSZ>>>(w2, b2);

    combine_kernel<<<(T_ * H_ / 4) / 256, 256>>>(out);
}

// round 6
// speedup vs baseline: 1.4752x; 1.4693x over previous
#include <cuda_runtime.h>
#include <cuda_bf16.h>
#include <cstdint>

#define E_ 8
#define H_ 1024
#define I_ 2048
#define T_ 1024

#define RST   40                     // smem row stride in bf16 elems (80B)
#define TILEB (128 * RST * 2)        // bytes per tile (128 rows) = 10240
#define STGB  (3 * TILEB)            // stage = A_hi + A_lo + B = 30720 B
#define NSTG  3
#define SMEMSZ (NSTG * STGB)         // 92160 B

// ---------------- scratch ----------------
__device__ int   g_cnt[E_];
__device__ int   g_tok[E_ * T_];
__device__ int   g_slot[E_ * T_];
__device__ float g_gate[E_ * T_];
__device__ __nv_bfloat16 g_xh[T_ * H_];
__device__ __nv_bfloat16 g_xl[T_ * H_];
__device__ __nv_bfloat16 g_acth[(size_t)E_ * T_ * I_];
__device__ __nv_bfloat16 g_actl[(size_t)E_ * T_ * I_];
__device__ float g_ypart[(size_t)T_ * 2 * H_];

// ---------------- helpers ----------------
__device__ __forceinline__ void cp16(uint32_t sa, const void* g) {
    asm volatile("cp.async.cg.shared.global [%0], [%1], 16;\n" :: "r"(sa), "l"(g));
}
__device__ __forceinline__ void cp_commit() { asm volatile("cp.async.commit_group;\n"); }
__device__ __forceinline__ void cp_wait1()  { asm volatile("cp.async.wait_group 1;\n"); }
__device__ __forceinline__ void cp_wait0()  { asm volatile("cp.async.wait_group 0;\n"); }

// pack two f32 -> bf16x2; 'lo' lands at the lower address half
__device__ __forceinline__ uint32_t pack_bf2(float lo, float hi) {
    uint32_t r;
    asm("cvt.rn.bf16x2.f32 %0, %1, %2;" : "=r"(r) : "f"(hi), "f"(lo));
    return r;
}
__device__ __forceinline__ float bf_rt(float v) {   // round-trip through bf16
    return __bfloat162float(__float2bfloat16_rn(v));
}
__device__ __forceinline__ void ldsm4(uint32_t r[4], uint32_t a) {
    asm volatile("ldmatrix.sync.aligned.m8n8.x4.shared.b16 {%0,%1,%2,%3}, [%4];"
        : "=r"(r[0]), "=r"(r[1]), "=r"(r[2]), "=r"(r[3]) : "r"(a));
}
__device__ __forceinline__ void hmma(float c[4], const uint32_t a[4], uint32_t b0, uint32_t b1) {
    asm volatile(
        "mma.sync.aligned.m16n8k16.row.col.f32.bf16.bf16.f32 "
        "{%0,%1,%2,%3}, {%4,%5,%6,%7}, {%8,%9}, {%0,%1,%2,%3};\n"
        : "+f"(c[0]), "+f"(c[1]), "+f"(c[2]), "+f"(c[3])
        : "r"(a[0]), "r"(a[1]), "r"(a[2]), "r"(a[3]), "r"(b0), "r"(b1));
}
__device__ __forceinline__ void sts128(uint32_t a, uint32_t u0, uint32_t u1, uint32_t u2, uint32_t u3) {
    asm volatile("st.shared.v4.b32 [%0], {%1,%2,%3,%4};"
        :: "r"(a), "r"(u0), "r"(u1), "r"(u2), "r"(u3));
}

// ---------------- small kernels ----------------
__global__ void zero_cnt_kernel() { if (threadIdx.x < E_) g_cnt[threadIdx.x] = 0; }

__global__ void presplit_kernel(const float* __restrict__ x) {
    int i = blockIdx.x * blockDim.x + threadIdx.x;    // over T_*H_/4
    float4 v = reinterpret_cast<const float4*>(x)[i];
    float h0 = bf_rt(v.x), h1 = bf_rt(v.y), h2 = bf_rt(v.z), h3 = bf_rt(v.w);
    uint2 hh = make_uint2(pack_bf2(v.x, v.y), pack_bf2(v.z, v.w));
    uint2 ll = make_uint2(pack_bf2(v.x - h0, v.y - h1), pack_bf2(v.z - h2, v.w - h3));
    reinterpret_cast<uint2*>(g_xh)[i] = hh;
    reinterpret_cast<uint2*>(g_xl)[i] = ll;
}

__global__ void router_kernel(const float* __restrict__ logits) {
    int t = blockIdx.x * blockDim.x + threadIdx.x;
    if (t >= T_) return;
    float l[E_]; float mx = -1e30f;
#pragma unroll
    for (int e = 0; e < E_; e++) { l[e] = logits[t * E_ + e]; mx = fmaxf(mx, l[e]); }
    float p[E_];
#pragma unroll
    for (int e = 0; e < E_; e++) p[e] = __expf(l[e] - mx);
    int i1 = 0, i2 = -1; float v1 = p[0], v2 = -1.0f;
#pragma unroll
    for (int e = 1; e < E_; e++) {
        float pe = p[e];
        if (pe > v1) { v2 = v1; i2 = i1; v1 = pe; i1 = e; }
        else if (pe > v2) { v2 = pe; i2 = e; }
    }
    float inv = 1.0f / (v1 + v2);
    int pos1 = atomicAdd(&g_cnt[i1], 1);
    g_tok[i1 * T_ + pos1] = t; g_slot[i1 * T_ + pos1] = 0; g_gate[i1 * T_ + pos1] = v1 * inv;
    int pos2 = atomicAdd(&g_cnt[i2], 1);
    g_tok[i2 * T_ + pos2] = t; g_slot[i2 * T_ + pos2] = 1; g_gate[i2 * T_ + pos2] = v2 * inv;
}

// =============== GEMM1: 128m x 64n (dual G|L), bf16 hi/lo, fused GLU ===============
__global__ void __launch_bounds__(256, 2) gemm1_kernel(
    const float* __restrict__ w13, const float* __restrict__ b13)
{
    int e = blockIdx.z;
    int cnt = g_cnt[e];
    int m0 = blockIdx.y * 128;
    if (m0 >= cnt) return;
    int n0 = blockIdx.x * 64;
    int tid = threadIdx.x;

    extern __shared__ char smem[];
    uint32_t sb = (uint32_t)__cvta_generic_to_shared(smem);

    // ---- fill setup: thread -> row lr, k-half lh ----
    int lr = tid >> 1, lh = tid & 1;
    int mg = m0 + lr; if (mg >= cnt) mg = cnt - 1;
    size_t axoff = (size_t)g_tok[e * T_ + mg] * H_ + lh * 16;
    const __nv_bfloat16* ah = g_xh + axoff;
    const __nv_bfloat16* al = g_xl + axoff;
    size_t brow = (lr < 64) ? ((size_t)e * 2 * I_ + n0 + lr)
                            : ((size_t)e * 2 * I_ + I_ + n0 + (lr - 64));
    const float4* bp = reinterpret_cast<const float4*>(w13 + brow * H_ + lh * 16);
    uint32_t adst = sb + lr * 80 + lh * 32;
    uint32_t bdst = sb + 2 * TILEB + lr * 80 + lh * 32;

    float f[16];
#define LDGB1(c) {                                                       \
        float4 v0_ = __ldg(bp + (c) * 8 + 0);                            \
        float4 v1_ = __ldg(bp + (c) * 8 + 1);                            \
        float4 v2_ = __ldg(bp + (c) * 8 + 2);                            \
        float4 v3_ = __ldg(bp + (c) * 8 + 3);                            \
        f[0]=v0_.x; f[1]=v0_.y; f[2]=v0_.z; f[3]=v0_.w;                  \
        f[4]=v1_.x; f[5]=v1_.y; f[6]=v1_.z; f[7]=v1_.w;                  \
        f[8]=v2_.x; f[9]=v2_.y; f[10]=v2_.z; f[11]=v2_.w;                \
        f[12]=v3_.x; f[13]=v3_.y; f[14]=v3_.z; f[15]=v3_.w; }
#define STSB(s) {                                                        \
        uint32_t d_ = bdst + (s) * STGB;                                 \
        sts128(d_, pack_bf2(f[0],f[1]), pack_bf2(f[2],f[3]),             \
                   pack_bf2(f[4],f[5]), pack_bf2(f[6],f[7]));            \
        sts128(d_ + 16, pack_bf2(f[8],f[9]), pack_bf2(f[10],f[11]),      \
                        pack_bf2(f[12],f[13]), pack_bf2(f[14],f[15])); }
#define FILLA(c, s) {                                                    \
        uint32_t d_ = adst + (s) * STGB;                                 \
        const __nv_bfloat16* ph_ = ah + (c) * 32;                        \
        const __nv_bfloat16* pl_ = al + (c) * 32;                        \
        cp16(d_, ph_); cp16(d_ + 16, ph_ + 8);                           \
        cp16(d_ + TILEB, pl_); cp16(d_ + TILEB + 16, pl_ + 8);           \
        cp_commit(); }

    // ---- compute setup ----
    int lane = tid & 31, warp = tid >> 5;
    int wm = warp & 3, wn = warp >> 2;      // 4m x 2n warps; warp 32m x 32n (G and L)
    int gid = lane >> 2, tig = lane & 3;

    uint32_t aAH = sb + (wm * 32 + (lane & 15)) * 80 + (lane >> 4) * 16;
    uint32_t aAL = aAH + TILEB;
    int brl = ((lane >> 4) & 1) * 8 + (lane & 7);
    int bko = ((lane >> 3) & 1) * 16;
    uint32_t bA = sb + 2 * TILEB + bko;
    uint32_t tb[4];
    tb[0] = bA + (wn * 32 + brl) * 80;
    tb[1] = bA + (wn * 32 + 16 + brl) * 80;
    tb[2] = bA + (64 + wn * 32 + brl) * 80;
    tb[3] = bA + (64 + wn * 32 + 16 + brl) * 80;

    float acc[2][8][4];
#pragma unroll
    for (int i = 0; i < 2; i++)
#pragma unroll
        for (int j = 0; j < 8; j++)
#pragma unroll
            for (int k = 0; k < 4; k++) acc[i][j][k] = 0.f;

    // ---- prologue ----
    LDGB1(0); STSB(0);
    LDGB1(1); STSB(1);
    FILLA(0, 0); FILLA(1, 1);

    const int NK = H_ / 32;   // 32
#pragma unroll 1
    for (int kt = 0; kt < NK; ++kt) {
        int st = kt % NSTG;
        if (kt + 1 < NK) cp_wait1(); else cp_wait0();
        __syncthreads();
        int cf = kt + 2;
        bool pf = cf < NK;
        int sf = cf % NSTG;
        if (pf) { LDGB1(cf); FILLA(cf, sf); }
        uint32_t so = st * STGB;
#pragma unroll
        for (int ks = 0; ks < 2; ks++) {
            uint32_t ko = so + ks * 32;
            uint32_t bf[4][4];
#pragma unroll
            for (int g = 0; g < 4; g++) ldsm4(bf[g], tb[g] + ko);
            uint32_t af[2][4];
            ldsm4(af[0], aAH + ko); ldsm4(af[1], aAH + ko + 1280);
#pragma unroll
            for (int g = 0; g < 4; g++)
#pragma unroll
                for (int mi = 0; mi < 2; mi++) {
                    hmma(acc[mi][2 * g],     af[mi], bf[g][0], bf[g][1]);
                    hmma(acc[mi][2 * g + 1], af[mi], bf[g][2], bf[g][3]);
                }
            ldsm4(af[0], aAL + ko); ldsm4(af[1], aAL + ko + 1280);
#pragma unroll
            for (int g = 0; g < 4; g++)
#pragma unroll
                for (int mi = 0; mi < 2; mi++) {
                    hmma(acc[mi][2 * g],     af[mi], bf[g][0], bf[g][1]);
                    hmma(acc[mi][2 * g + 1], af[mi], bf[g][2], bf[g][3]);
                }
        }
        if (pf) STSB(sf);
    }

    // ---- epilogue: bias + GLU + bf16 hi/lo split store ----
    float bgv[4][2], blv[4][2];
#pragma unroll
    for (int ni = 0; ni < 4; ni++) {
        int n = n0 + wn * 32 + ni * 8 + tig * 2;
        bgv[ni][0] = __ldg(&b13[(size_t)e * 2 * I_ + n]);
        bgv[ni][1] = __ldg(&b13[(size_t)e * 2 * I_ + n + 1]);
        blv[ni][0] = __ldg(&b13[(size_t)e * 2 * I_ + I_ + n]);
        blv[ni][1] = __ldg(&b13[(size_t)e * 2 * I_ + I_ + n + 1]);
    }
    size_t actbase = (size_t)e * T_ * I_;
#pragma unroll
    for (int mi = 0; mi < 2; mi++) {
#pragma unroll
        for (int rr = 0; rr < 2; rr++) {
            int m = m0 + wm * 32 + mi * 16 + gid + rr * 8;
            if (m >= cnt) continue;
            size_t rowoff = actbase + (size_t)m * I_;
#pragma unroll
            for (int ni = 0; ni < 4; ni++) {
                int n = n0 + wn * 32 + ni * 8 + tig * 2;
                float g0 = acc[mi][ni][rr * 2 + 0] + bgv[ni][0];
                float g1 = acc[mi][ni][rr * 2 + 1] + bgv[ni][1];
                float l0 = acc[mi][4 + ni][rr * 2 + 0] + blv[ni][0];
                float l1 = acc[mi][4 + ni][rr * 2 + 1] + blv[ni][1];
                float a0 = g0 * (1.f / (1.f + __expf(-1.702f * g0))) * (l0 + 1.0f);
                float a1 = g1 * (1.f / (1.f + __expf(-1.702f * g1))) * (l1 + 1.0f);
                float h0 = bf_rt(a0), h1 = bf_rt(a1);
                *reinterpret_cast<uint32_t*>(g_acth + rowoff + n) = pack_bf2(a0, a1);
                *reinterpret_cast<uint32_t*>(g_actl + rowoff + n) = pack_bf2(a0 - h0, a1 - h1);
            }
        }
    }
#undef LDGB1
#undef STSB
#undef FILLA
}

// =============== GEMM2: 128m x 128n, bf16 hi/lo, fused bias+gate+scatter ===============
__global__ void __launch_bounds__(256, 2) gemm2_kernel(
    const float* __restrict__ w2, const float* __restrict__ b2)
{
    int e = blockIdx.z;
    int cnt = g_cnt[e];
    int m0 = blockIdx.y * 128;
    if (m0 >= cnt) return;
    int n0 = blockIdx.x * 128;
    int tid = threadIdx.x;

    extern __shared__ char smem[];
    uint32_t sb = (uint32_t)__cvta_generic_to_shared(smem);

    int lr = tid >> 1, lh = tid & 1;
    size_t aoff = (size_t)(e * T_ + m0 + lr) * I_ + lh * 16;
    const __nv_bfloat16* ah = g_acth + aoff;
    const __nv_bfloat16* al = g_actl + aoff;
    const float4* bp = reinterpret_cast<const float4*>(
        w2 + (size_t)(e * H_ + n0 + lr) * I_ + lh * 16);
    uint32_t adst = sb + lr * 80 + lh * 32;
    uint32_t bdst = sb + 2 * TILEB + lr * 80 + lh * 32;

    float f[16];
#define LDGB2(c) {                                                       \
        float4 v0_ = __ldg(bp + (c) * 8 + 0);                            \
        float4 v1_ = __ldg(bp + (c) * 8 + 1);                            \
        float4 v2_ = __ldg(bp + (c) * 8 + 2);                            \
        float4 v3_ = __ldg(bp + (c) * 8 + 3);                            \
        f[0]=v0_.x; f[1]=v0_.y; f[2]=v0_.z; f[3]=v0_.w;                  \
        f[4]=v1_.x; f[5]=v1_.y; f[6]=v1_.z; f[7]=v1_.w;                  \
        f[8]=v2_.x; f[9]=v2_.y; f[10]=v2_.z; f[11]=v2_.w;                \
        f[12]=v3_.x; f[13]=v3_.y; f[14]=v3_.z; f[15]=v3_.w; }
#define STSB2(s) {                                                       \
        uint32_t d_ = bdst + (s) * STGB;                                 \
        sts128(d_, pack_bf2(f[0],f[1]), pack_bf2(f[2],f[3]),             \
                   pack_bf2(f[4],f[5]), pack_bf2(f[6],f[7]));            \
        sts128(d_ + 16, pack_bf2(f[8],f[9]), pack_bf2(f[10],f[11]),      \
                        pack_bf2(f[12],f[13]), pack_bf2(f[14],f[15])); }
#define FILLA2(c, s) {                                                   \
        uint32_t d_ = adst + (s) * STGB;                                 \
        const __nv_bfloat16* ph_ = ah + (c) * 32;                        \
        const __nv_bfloat16* pl_ = al + (c) * 32;                        \
        cp16(d_, ph_); cp16(d_ + 16, ph_ + 8);                           \
        cp16(d_ + TILEB, pl_); cp16(d_ + TILEB + 16, pl_ + 8);           \
        cp_commit(); }

    int lane = tid & 31, warp = tid >> 5;
    int wm = warp & 3, wn = warp >> 2;      // 4m x 2n; warp 32m x 64n
    int gid = lane >> 2, tig = lane & 3;

    uint32_t aAH = sb + (wm * 32 + (lane & 15)) * 80 + (lane >> 4) * 16;
    uint32_t aAL = aAH + TILEB;
    int brl = ((lane >> 4) & 1) * 8 + (lane & 7);
    int bko = ((lane >> 3) & 1) * 16;
    uint32_t bA = sb + 2 * TILEB + bko;
    uint32_t tb[4];
#pragma unroll
    for (int g = 0; g < 4; g++) tb[g] = bA + (wn * 64 + g * 16 + brl) * 80;

    float acc[2][8][4];
#pragma unroll
    for (int i = 0; i < 2; i++)
#pragma unroll
        for (int j = 0; j < 8; j++)
#pragma unroll
            for (int k = 0; k < 4; k++) acc[i][j][k] = 0.f;

    LDGB2(0); STSB2(0);
    LDGB2(1); STSB2(1);
    FILLA2(0, 0); FILLA2(1, 1);

    const int NK = I_ / 32;   // 64
#pragma unroll 1
    for (int kt = 0; kt < NK; ++kt) {
        int st = kt % NSTG;
        if (kt + 1 < NK) cp_wait1(); else cp_wait0();
        __syncthreads();
        int cf = kt + 2;
        bool pf = cf < NK;
        int sf = cf % NSTG;
        if (pf) { LDGB2(cf); FILLA2(cf, sf); }
        uint32_t so = st * STGB;
#pragma unroll
        for (int ks = 0; ks < 2; ks++) {
            uint32_t ko = so + ks * 32;
            uint32_t bf[4][4];
#pragma unroll
            for (int g = 0; g < 4; g++) ldsm4(bf[g], tb[g] + ko);
            uint32_t af[2][4];
            ldsm4(af[0], aAH + ko); ldsm4(af[1], aAH + ko + 1280);
#pragma unroll
            for (int g = 0; g < 4; g++)
#pragma unroll
                for (int mi = 0; mi < 2; mi++) {
                    hmma(acc[mi][2 * g],     af[mi], bf[g][0], bf[g][1]);
                    hmma(acc[mi][2 * g + 1], af[mi], bf[g][2], bf[g][3]);
                }
            ldsm4(af[0], aAL + ko); ldsm4(af[1], aAL + ko + 1280);
#pragma unroll
            for (int g = 0; g < 4; g++)
#pragma unroll
                for (int mi = 0; mi < 2; mi++) {
                    hmma(acc[mi][2 * g],     af[mi], bf[g][0], bf[g][1]);
                    hmma(acc[mi][2 * g + 1], af[mi], bf[g][2], bf[g][3]);
                }
        }
        if (pf) STSB2(sf);
    }

    float bv[8][2];
#pragma unroll
    for (int ni = 0; ni < 8; ni++) {
        int n = n0 + wn * 64 + ni * 8 + tig * 2;
        bv[ni][0] = __ldg(&b2[(size_t)e * H_ + n]);
        bv[ni][1] = __ldg(&b2[(size_t)e * H_ + n + 1]);
    }
#pragma unroll
    for (int mi = 0; mi < 2; mi++) {
#pragma unroll
        for (int rr = 0; rr < 2; rr++) {
            int m = m0 + wm * 32 + mi * 16 + gid + rr * 8;
            if (m >= cnt) continue;
            int tok = g_tok[e * T_ + m];
            int slot = g_slot[e * T_ + m];
            float gt = g_gate[e * T_ + m];
            float* dst = g_ypart + (size_t)(tok * 2 + slot) * H_;
#pragma unroll
            for (int ni = 0; ni < 8; ni++) {
                int n = n0 + wn * 64 + ni * 8 + tig * 2;
                float v0 = (acc[mi][ni][rr * 2 + 0] + bv[ni][0]) * gt;
                float v1 = (acc[mi][ni][rr * 2 + 1] + bv[ni][1]) * gt;
                *reinterpret_cast<float2*>(dst + n) = make_float2(v0, v1);
            }
        }
    }
#undef LDGB2
#undef STSB2
#undef FILLA2
}

// ---------------- deterministic combine ----------------
__global__ void combine_kernel(float* __restrict__ out) {
    int i = blockIdx.x * blockDim.x + threadIdx.x;
    const int HV = H_ / 4;
    int t = i / HV;
    int h = i - t * HV;
    const float4* p0 = reinterpret_cast<const float4*>(g_ypart) + (size_t)(2 * t) * HV + h;
    const float4* p1 = p0 + HV;
    float4 a = *p0, b = *p1;
    reinterpret_cast<float4*>(out)[i] = make_float4(a.x + b.x, a.y + b.y, a.z + b.z, a.w + b.w);
}

// ---------------- launch ----------------
extern "C" void kernel_launch(void* const* d_in, const int* in_sizes, int n_in,
                              void* d_out, int out_size) {
    const float* x      = (const float*)d_in[0];
    const float* logits = (const float*)d_in[1];
    const float* w13    = (const float*)d_in[2];
    const float* w2     = (const float*)d_in[3];
    const float* b13    = (const float*)d_in[4];
    const float* b2     = (const float*)d_in[5];
    float* out = (float*)d_out;

    static int attr_done = 0;
    if (!attr_done) {
        cudaFuncSetAttribute(gemm1_kernel, cudaFuncAttributeMaxDynamicSharedMemorySize, SMEMSZ);
        cudaFuncSetAttribute(gemm2_kernel, cudaFuncAttributeMaxDynamicSharedMemorySize, SMEMSZ);
        attr_done = 1;
    }

    zero_cnt_kernel<<<1, 32>>>();
    presplit_kernel<<<(T_ * H_ / 4) / 256, 256>>>(x);
    router_kernel<<<T_ / 256, 256>>>(logits);

    dim3 g1(I_ / 64, T_ / 128, E_);    // 32 x 8 x 8
    gemm1_kernel<<<g1, 256, SMEMSZ>>>(w13, b13);

    dim3 g2(H_ / 128, T_ / 128, E_);   // 8 x 8 x 8
    gemm2_kernel<<<g2, 256, SMEMSZ>>>(w2, b2);

    combine_kernel<<<(T_ * H_ / 4) / 256, 256>>>(out);
}